// round 10
// baseline (speedup 1.0000x reference)
#include <cuda_runtime.h>

#define NB 1024
#define LW 40
#define DIM 128
#define WIN 5
#define NPAIR 370
#define NEG 5
#define NNEG (NPAIR*NEG)      // 1850
#define NROWS (NB*LW)         // 40960 flat walk positions

// int8-quantized ctx rows (128 B/row = 8 uint4) + per-row scales.
__device__ uint4 g_ctx_i8[NROWS * 8];     // 5.24 MB
__device__ float g_ctx_sc[NROWS];         // per-row ctx scale (amax/127)
__device__ float    g_accum = 0.f;
__device__ unsigned g_count = 0u;

__device__ __forceinline__ int dp16(uint4 a, uint4 b) {
    int acc = __dp4a((int)a.x, (int)b.x, 0);
    acc = __dp4a((int)a.y, (int)b.y, acc);
    acc = __dp4a((int)a.z, (int)b.z, acc);
    acc = __dp4a((int)a.w, (int)b.w, acc);
    return acc;
}

__device__ __forceinline__ unsigned pack4(float4 v, float rs) {
    int q0 = __float2int_rn(v.x * rs);
    int q1 = __float2int_rn(v.y * rs);
    int q2 = __float2int_rn(v.z * rs);
    int q3 = __float2int_rn(v.w * rs);
    return (q0 & 0xff) | ((q1 & 0xff) << 8) | ((q2 & 0xff) << 16) | (q3 << 24);
}

// K1: one warp per flat walk row — quantize ctx rows per-row.
__global__ __launch_bounds__(256) void precompute_kernel(
    const float* __restrict__ ctx_embed,
    const int*   __restrict__ batch_walk)
{
    const int row  = (blockIdx.x * blockDim.x + threadIdx.x) >> 5;
    const int lane = threadIdx.x & 31;
    if (row >= NROWS) return;
    const int id = __ldg(batch_walk + row);
    float4 vc = *(const float4*)(ctx_embed + (size_t)id * DIM + lane * 4);

    float ac = fmaxf(fmaxf(fabsf(vc.x), fabsf(vc.y)), fmaxf(fabsf(vc.z), fabsf(vc.w)));
    #pragma unroll
    for (int o = 16; o > 0; o >>= 1)
        ac = fmaxf(ac, __shfl_xor_sync(0xffffffffu, ac, o));
    ac = fmaxf(ac, 1e-30f);

    ((unsigned*)g_ctx_i8)[(size_t)row * 32 + lane] = pack4(vc, 127.f / ac);
    if (lane == 0) g_ctx_sc[row] = ac * (1.f / 127.f);
}

__global__ __launch_bounds__(256) void walk_kernel(
    const float* __restrict__ node_embed,
    const int*   __restrict__ batch_walk,
    const int*   __restrict__ neg_dst_idx,  // [NB*NNEG]
    float*       __restrict__ out)
{
    __shared__ uint4          node_s8 [LW * 8];    // 5120 B (int8 rows)
    __shared__ uint4          ctx_s8  [LW * 8];    // 5120 B
    __shared__ float          nsc_s   [LW];        // node per-row scale
    __shared__ float          csc_s   [LW];        // ctx per-row scale (walk rows)
    __shared__ int            nid_s   [NNEG];      // 7400 B
    __shared__ float          negsc_s [NNEG + 8];  // 7432 B (padded)
    __shared__ unsigned short pair_s  [NPAIR];     //  740 B
    __shared__ float          wsum    [8];         // ~26.3 KB total

    const int b   = blockIdx.x;
    const int tid = threadIdx.x;
    const int warp = tid >> 5, lane = tid & 31;

    // Pair table in reference order (closed-form offsets) + walk ctx scales.
    if (tid < LW) {
        const int i = tid;
        int cum;
        if (i <= 5)       cum = 5 * i + (i * (i - 1)) / 2;
        else if (i <= 35) cum = 35 + 10 * (i - 5);
        else { int m = i - 35; cum = 335 + 9 * m - (m * (m - 1)) / 2; }
        int lo = i - WIN; if (lo < 0) lo = 0;
        int hi = i + 1 + WIN; if (hi > LW) hi = LW;
        for (int j = lo; j < i; j++)     pair_s[cum++] = (unsigned short)(j | (i << 8));
        for (int j = i + 1; j < hi; j++) pair_s[cum++] = (unsigned short)(j | (i << 8));
        csc_s[tid] = g_ctx_sc[b * LW + tid];
    }

    // Gather + quantize this walk's node rows directly from node_embed (warp/row).
    for (int r = warp; r < LW; r += 8) {
        const int id = __ldg(batch_walk + b * LW + r);
        float4 vn = *(const float4*)(node_embed + (size_t)id * DIM + lane * 4);
        float an = fmaxf(fmaxf(fabsf(vn.x), fabsf(vn.y)), fmaxf(fabsf(vn.z), fabsf(vn.w)));
        #pragma unroll
        for (int o = 16; o > 0; o >>= 1)
            an = fmaxf(an, __shfl_xor_sync(0xffffffffu, an, o));
        an = fmaxf(an, 1e-30f);
        ((unsigned*)node_s8)[r * 32 + lane] = pack4(vn, 127.f / an);
        if (lane == 0) nsc_s[r] = an * (1.f / 127.f);
    }

    // Copy this walk's quantized ctx rows from the table (L2-hot).
    {
        const uint4* gc = g_ctx_i8 + (size_t)b * LW * 8;
        for (int t = tid; t < LW * 8; t += 256) ctx_s8[t] = gc[t];
    }
    // Stage negative indices AND their ctx scales (scattered 4B gathers, high MLP here).
    {
        const int* nd = neg_dst_idx + b * NNEG;
        for (int n = tid; n < NNEG; n += 256) {
            int ni = nd[n];
            nid_s[n]   = ni;
            negsc_s[n] = g_ctx_sc[ni];
        }
        if (tid < 8) negsc_s[NNEG + tid] = 0.f;
    }
    __syncthreads();

    const int grp = lane >> 3, j = lane & 7;    // 4 groups of 8 lanes per warp
    float acc = 0.f;

    // Each 8-lane group handles one PAIR (1 pos + 5 negs) per iteration.
    #pragma unroll 1
    for (int it = 0; it < 12; it++) {
        const int p = it * 32 + warp * 4 + grp;
        const bool valid = (p < NPAIR);
        const int pe = valid ? p : 0;
        const int pk = pair_s[pe];
        const int s = pk & 0xff, d = pk >> 8;

        // Rows: 1 LDS.128 each (lane j takes uint4 j of the 128-B row).
        const uint4 qs = node_s8[s * 8 + j];    // node_src
        const uint4 qd = node_s8[d * 8 + j];    // node_dst (reused x5)
        const uint4 qc = ctx_s8 [d * 8 + j];    // ctx_dst

        int ip[6];
        ip[0] = dp16(qs, qc);                   // positive

        // 5 negatives: 1 LDG.128 per row (L2-resident int8 rows).
        uint4 cg[NEG];
        #pragma unroll
        for (int k = 0; k < NEG; k++)
            cg[k] = g_ctx_i8[(size_t)nid_s[pe * NEG + k] * 8 + j];
        #pragma unroll
        for (int k = 0; k < NEG; k++)
            ip[1 + k] = dp16(qd, cg[k]);

        // Reduce 6 int scores across the 8-lane group (exact).
        #pragma unroll
        for (int k = 0; k < 6; k++) {
            int v = ip[k];
            v += __shfl_xor_sync(0xffffffffu, v, 4);
            v += __shfl_xor_sync(0xffffffffu, v, 2);
            v += __shfl_xor_sync(0xffffffffu, v, 1);
            ip[k] = v;
        }

        // Park score j on lane j; scales from SMEM only.
        int iv = ip[0];
        iv = (j == 1) ? ip[1] : iv;
        iv = (j == 2) ? ip[2] : iv;
        iv = (j == 3) ? ip[3] : iv;
        iv = (j == 4) ? ip[4] : iv;
        iv = (j == 5) ? ip[5] : iv;

        const float sA = nsc_s[(j == 0) ? s : d];
        const float sB = (j == 0) ? csc_s[d] : negsc_s[pe * NEG + (j - 1)];

        float x = (float)iv * sA * sB;
        x = fminf(fmaxf(x, -6.f), 6.f);
        if (j == 0) x = -x;                       // pos: softplus(-v)
        if (j >= 6 || !valid) x = -1e30f;
        acc += __logf(1.f + __expf(x));
    }

    // Warp total, CTA total, global atomic.
    #pragma unroll
    for (int o = 16; o > 0; o >>= 1) acc += __shfl_xor_sync(0xffffffffu, acc, o);
    if (lane == 0) wsum[warp] = acc;
    __syncthreads();
    if (tid == 0) {
        float sum = 0.f;
        #pragma unroll
        for (int w = 0; w < 8; w++) sum += wsum[w];
        atomicAdd(&g_accum, sum);
        __threadfence();
        unsigned old = atomicAdd(&g_count, 1u);
        if (old == NB - 1) {
            float total = atomicExch(&g_accum, 0.f);
            out[0] = total * (1.0f / (float)(NB * NPAIR));
            atomicExch(&g_count, 0u);
        }
    }
}

extern "C" void kernel_launch(void* const* d_in, const int* in_sizes, int n_in,
                              void* d_out, int out_size) {
    const float* node_embed  = (const float*)d_in[0];
    const float* ctx_embed   = (const float*)d_in[1];
    const int*   batch_walk  = (const int*)d_in[2];
    const int*   neg_dst_idx = (const int*)d_in[3];
    float*       out         = (float*)d_out;

    precompute_kernel<<<(NROWS * 32 + 255) / 256, 256>>>(ctx_embed, batch_walk);
    walk_kernel<<<NB, 256>>>(node_embed, batch_walk, neg_dst_idx, out);
}

// round 11
// speedup vs baseline: 1.0031x; 1.0031x over previous
#include <cuda_runtime.h>

#define NB 1024
#define LW 40
#define DIM 128
#define WIN 5
#define NPAIR 370
#define NEG 5
#define NNEG (NPAIR*NEG)      // 1850
#define NROWS (NB*LW)         // 40960 flat walk positions

// int8-quantized node/ctx rows (128 B/row = 8 uint4) + per-row scales.
__device__ uint4 g_node_i8[NROWS * 8];     // 5.24 MB
__device__ uint4 g_ctx_i8 [NROWS * 8];     // 5.24 MB
__device__ float g_node_sc[NROWS];
__device__ float g_ctx_sc [NROWS];
__device__ float    g_accum = 0.f;
__device__ unsigned g_count = 0u;

__device__ __forceinline__ int dp16(uint4 a, uint4 b) {
    int acc = __dp4a((int)a.x, (int)b.x, 0);
    acc = __dp4a((int)a.y, (int)b.y, acc);
    acc = __dp4a((int)a.z, (int)b.z, acc);
    acc = __dp4a((int)a.w, (int)b.w, acc);
    return acc;
}

__device__ __forceinline__ unsigned pack4(float4 v, float rs) {
    int q0 = __float2int_rn(v.x * rs);
    int q1 = __float2int_rn(v.y * rs);
    int q2 = __float2int_rn(v.z * rs);
    int q3 = __float2int_rn(v.w * rs);
    return (q0 & 0xff) | ((q1 & 0xff) << 8) | ((q2 & 0xff) << 16) | (q3 << 24);
}

// One warp per flat walk row: amax -> int8 quantize node+ctx rows.
__global__ __launch_bounds__(256) void precompute_kernel(
    const float* __restrict__ node_embed,
    const float* __restrict__ ctx_embed,
    const int*   __restrict__ batch_walk)
{
    const int row  = (blockIdx.x * blockDim.x + threadIdx.x) >> 5;
    const int lane = threadIdx.x & 31;
    if (row >= NROWS) return;
    const int id = __ldg(batch_walk + row);
    float4 vn = *(const float4*)(node_embed + (size_t)id * DIM + lane * 4);
    float4 vc = *(const float4*)(ctx_embed  + (size_t)id * DIM + lane * 4);

    float an = fmaxf(fmaxf(fabsf(vn.x), fabsf(vn.y)), fmaxf(fabsf(vn.z), fabsf(vn.w)));
    float ac = fmaxf(fmaxf(fabsf(vc.x), fabsf(vc.y)), fmaxf(fabsf(vc.z), fabsf(vc.w)));
    #pragma unroll
    for (int o = 16; o > 0; o >>= 1) {
        an = fmaxf(an, __shfl_xor_sync(0xffffffffu, an, o));
        ac = fmaxf(ac, __shfl_xor_sync(0xffffffffu, ac, o));
    }
    an = fmaxf(an, 1e-30f);
    ac = fmaxf(ac, 1e-30f);

    ((unsigned*)g_node_i8)[(size_t)row * 32 + lane] = pack4(vn, 127.f / an);
    ((unsigned*)g_ctx_i8 )[(size_t)row * 32 + lane] = pack4(vc, 127.f / ac);
    if (lane == 0) {
        g_node_sc[row] = an * (1.f / 127.f);
        g_ctx_sc [row] = ac * (1.f / 127.f);
    }
}

__global__ __launch_bounds__(256) void walk_kernel(
    const int* __restrict__ neg_dst_idx,  // [NB*NNEG]
    float*     __restrict__ out)
{
    __shared__ uint4          node_s8 [LW * 8];    // 5120 B (int8 rows)
    __shared__ uint4          ctx_s8  [LW * 8];    // 5120 B
    __shared__ float          nsc_s   [LW];
    __shared__ float          csc_s   [LW];
    __shared__ int            nid_s   [NNEG];      // 7400 B
    __shared__ float          negsc_s [NNEG + 8];  // 7432 B (padded)
    __shared__ unsigned short pair_s  [NPAIR];     //  740 B
    __shared__ float          wsum    [8];         // ~26.3 KB total

    const int b   = blockIdx.x;
    const int tid = threadIdx.x;
    const int warp = tid >> 5, lane = tid & 31;

    // Pair table in reference order (closed-form offsets) + walk-row scales.
    if (tid < LW) {
        const int i = tid;
        int cum;
        if (i <= 5)       cum = 5 * i + (i * (i - 1)) / 2;
        else if (i <= 35) cum = 35 + 10 * (i - 5);
        else { int m = i - 35; cum = 335 + 9 * m - (m * (m - 1)) / 2; }
        int lo = i - WIN; if (lo < 0) lo = 0;
        int hi = i + 1 + WIN; if (hi > LW) hi = LW;
        for (int j = lo; j < i; j++)     pair_s[cum++] = (unsigned short)(j | (i << 8));
        for (int j = i + 1; j < hi; j++) pair_s[cum++] = (unsigned short)(j | (i << 8));
        nsc_s[tid] = g_node_sc[b * LW + tid];
        csc_s[tid] = g_ctx_sc [b * LW + tid];
    }

    // Copy this walk's int8 rows from the tables (L2-hot, coalesced uint4).
    {
        const uint4* gn = g_node_i8 + (size_t)b * LW * 8;
        const uint4* gc = g_ctx_i8  + (size_t)b * LW * 8;
        for (int t = tid; t < LW * 8; t += 256) {
            node_s8[t] = gn[t];
            ctx_s8 [t] = gc[t];
        }
    }
    // Stage negative indices AND their ctx scales (scattered 4B L2-hot gathers, high MLP).
    {
        const int* nd = neg_dst_idx + b * NNEG;
        for (int n = tid; n < NNEG; n += 256) {
            int ni = nd[n];
            nid_s[n]   = ni;
            negsc_s[n] = g_ctx_sc[ni];
        }
        if (tid < 8) negsc_s[NNEG + tid] = 0.f;
    }
    __syncthreads();

    const int grp = lane >> 3, j = lane & 7;    // 4 groups of 8 lanes per warp
    float acc = 0.f;

    // Each 8-lane group handles one PAIR (1 pos + 5 negs) per iteration.
    #pragma unroll 1
    for (int it = 0; it < 12; it++) {
        const int p = it * 32 + warp * 4 + grp;
        const bool valid = (p < NPAIR);
        const int pe = valid ? p : 0;
        const int pk = pair_s[pe];
        const int s = pk & 0xff, d = pk >> 8;

        // Rows: 1 LDS.128 each (lane j takes uint4 j of the 128-B row).
        const uint4 qs = node_s8[s * 8 + j];    // node_src
        const uint4 qd = node_s8[d * 8 + j];    // node_dst (reused x5)
        const uint4 qc = ctx_s8 [d * 8 + j];    // ctx_dst

        int ip[6];
        ip[0] = dp16(qs, qc);                   // positive

        // 5 negatives: 1 LDG.128 per row (L2-resident int8 rows).
        uint4 cg[NEG];
        #pragma unroll
        for (int k = 0; k < NEG; k++)
            cg[k] = g_ctx_i8[(size_t)nid_s[pe * NEG + k] * 8 + j];
        #pragma unroll
        for (int k = 0; k < NEG; k++)
            ip[1 + k] = dp16(qd, cg[k]);

        // Reduce 6 int scores across the 8-lane group (exact).
        #pragma unroll
        for (int k = 0; k < 6; k++) {
            int v = ip[k];
            v += __shfl_xor_sync(0xffffffffu, v, 4);
            v += __shfl_xor_sync(0xffffffffu, v, 2);
            v += __shfl_xor_sync(0xffffffffu, v, 1);
            ip[k] = v;
        }

        // Park score j on lane j; all scales from SMEM.
        int iv = ip[0];
        iv = (j == 1) ? ip[1] : iv;
        iv = (j == 2) ? ip[2] : iv;
        iv = (j == 3) ? ip[3] : iv;
        iv = (j == 4) ? ip[4] : iv;
        iv = (j == 5) ? ip[5] : iv;

        const float sA = nsc_s[(j == 0) ? s : d];
        const float sB = (j == 0) ? csc_s[d] : negsc_s[pe * NEG + (j - 1)];

        float x = (float)iv * sA * sB;
        x = fminf(fmaxf(x, -6.f), 6.f);
        if (j == 0) x = -x;                       // pos: softplus(-v)
        if (j >= 6 || !valid) x = -1e30f;
        acc += __logf(1.f + __expf(x));
    }

    // Warp total, CTA total, global atomic.
    #pragma unroll
    for (int o = 16; o > 0; o >>= 1) acc += __shfl_xor_sync(0xffffffffu, acc, o);
    if (lane == 0) wsum[warp] = acc;
    __syncthreads();
    if (tid == 0) {
        float sum = 0.f;
        #pragma unroll
        for (int w = 0; w < 8; w++) sum += wsum[w];
        atomicAdd(&g_accum, sum);
        __threadfence();
        unsigned old = atomicAdd(&g_count, 1u);
        if (old == NB - 1) {
            float total = atomicExch(&g_accum, 0.f);
            out[0] = total * (1.0f / (float)(NB * NPAIR));
            atomicExch(&g_count, 0u);
        }
    }
}

extern "C" void kernel_launch(void* const* d_in, const int* in_sizes, int n_in,
                              void* d_out, int out_size) {
    const float* node_embed  = (const float*)d_in[0];
    const float* ctx_embed   = (const float*)d_in[1];
    const int*   batch_walk  = (const int*)d_in[2];
    const int*   neg_dst_idx = (const int*)d_in[3];
    float*       out         = (float*)d_out;

    precompute_kernel<<<(NROWS * 32 + 255) / 256, 256>>>(node_embed, ctx_embed, batch_walk);
    walk_kernel<<<NB, 256>>>(neg_dst_idx, out);
}